// round 17
// baseline (speedup 1.0000x reference)
#include <cuda_runtime.h>
#include <cuda_fp16.h>
#include <cstdint>
#include <cstddef>

#define DIM    1024
#define ALPHA  64
#define NROWS  32768
#define SCALE  0.03125f        // 1/sqrt(1024)
#define TILE_ROWS 128
#define NCTA   (NROWS / TILE_ROWS)

// operand pre-scales (powers of 2, folded out exactly)
#define MT_S   256.0f
#define INV_MT (1.0f / 256.0f)
#define A_S    1024.0f
#define CV_S   64.0f
#define OUT_S  (1.0f / (1024.0f * 64.0f))

// smem layout (bytes), aliased by lifetime:
//   phase1: xs[2][128][72]h @0 (36864), mts[2][64][72]h @36864 (18432)
//   softmax: pm[128][2]f @0, ps[128][2]f @1024      [xs dead]
//   A hi:   ahs[128][72]h @55296 (18432)            [alive thru phase3]
//   phase3: cvs[2][64][72]h @73728 (18432)          [dedicated]
#define XS_OFF   0
#define MTS_OFF  36864
#define PM_OFF   0
#define PS_OFF   1024
#define AH_OFF   55296
#define CVS_OFF  73728
#define BIAS_OFF 92160
#define SMEM_BYTES 92416

#define KSPLIT 64
__device__ float  g_part[KSPLIT * ALPHA * DIM];     // 16MB scratch
__device__ float  g_bias[ALPHA];
__device__ __half g_Mth[ALPHA * DIM];           // Mt[a][d] * 256
__device__ __half g_CVh[DIM * ALPHA];           // C_V[d][a]*64

// ---------------- helpers ----------------
__device__ __forceinline__ uint32_t fpack(float a, float b) {
    __half2 h = __floats2half2_rn(a, b);
    return *reinterpret_cast<uint32_t*>(&h);
}
__device__ __forceinline__ void mma16816(float* c, const uint32_t* a, const uint32_t* b) {
    asm volatile("mma.sync.aligned.m16n8k16.row.col.f32.f16.f16.f32 "
        "{%0,%1,%2,%3}, {%4,%5,%6,%7}, {%8,%9}, {%0,%1,%2,%3};"
        : "+f"(c[0]), "+f"(c[1]), "+f"(c[2]), "+f"(c[3])
        : "r"(a[0]), "r"(a[1]), "r"(a[2]), "r"(a[3]), "r"(b[0]), "r"(b[1]));
}
__device__ __forceinline__ void ldsm_x4(uint32_t* r, const __half* p) {
    uint32_t a = (uint32_t)__cvta_generic_to_shared(p);
    asm volatile("ldmatrix.sync.aligned.m8n8.x4.shared.b16 {%0,%1,%2,%3}, [%4];"
        : "=r"(r[0]), "=r"(r[1]), "=r"(r[2]), "=r"(r[3]) : "r"(a));
}
__device__ __forceinline__ void cp_async16(void* dst, const void* src) {
    uint32_t s = (uint32_t)__cvta_generic_to_shared(dst);
    asm volatile("cp.async.cg.shared.global [%0], [%1], 16;" :: "r"(s), "l"(src));
}
#define CP_COMMIT() asm volatile("cp.async.commit_group;" ::: "memory")
#define CP_WAIT0()  asm volatile("cp.async.wait_group 0;" ::: "memory")

// ---------------- prep: partial GEMM  Mt_part = C_K^T @ W_Q (K-split 64x16) ----------------
__global__ __launch_bounds__(256) void prep_partial(
    const float* __restrict__ W_Q, const float* __restrict__ C_K)
{
    __shared__ float ck_s[16][68];
    __shared__ float wq_s[16][68];
    const int tid = threadIdx.x;
    const int nb = blockIdx.x & 15, kb = blockIdx.x >> 4;
    const int e0 = kb * 16, d0 = nb * 64;
    {
        const int e = tid >> 4, q = tid & 15;
        *(float4*)&ck_s[e][q * 4] = *(const float4*)&C_K[(e0 + e) * ALPHA + q * 4];
        *(float4*)&wq_s[e][q * 4] = *(const float4*)&W_Q[(size_t)(e0 + e) * DIM + d0 + q * 4];
    }
    __syncthreads();
    const int tx = tid & 15, ty = tid >> 4;
    float acc[4][4] = {};
    #pragma unroll
    for (int e = 0; e < 16; e++) {
        const float4 av = *(const float4*)&ck_s[e][ty * 4];
        const float4 bv = *(const float4*)&wq_s[e][tx * 4];
        const float aa[4] = {av.x, av.y, av.z, av.w};
        const float bb[4] = {bv.x, bv.y, bv.z, bv.w};
        #pragma unroll
        for (int i = 0; i < 4; i++)
            #pragma unroll
            for (int j = 0; j < 4; j++) acc[i][j] += aa[i] * bb[j];
    }
    #pragma unroll
    for (int i = 0; i < 4; i++) {
        float4 w; w.x = acc[i][0]; w.y = acc[i][1]; w.z = acc[i][2]; w.w = acc[i][3];
        *(float4*)&g_part[kb * (ALPHA * DIM) + (ty * 4 + i) * DIM + d0 + tx * 4] = w;
    }
}

// ---------------- prep: reduce + convert ----------------
__global__ __launch_bounds__(256) void prep_reduce(
    const float* __restrict__ b_Q, const float* __restrict__ C_K,
    const float* __restrict__ C_V)
{
    __shared__ float red[256];
    const int tid = threadIdx.x;
    if (blockIdx.x == 256) {                         // bias block
        const int a = tid & 63, ks = tid >> 6;
        float s = 0.f;
        for (int e = ks * 256; e < ks * 256 + 256; e++)
            s += b_Q[e] * C_K[e * ALPHA + a];
        red[tid] = s;
        __syncthreads();
        if (tid < 64)
            g_bias[tid] = (red[tid] + red[tid + 64] + red[tid + 128] + red[tid + 192]) * SCALE;
        return;
    }
    const int o = blockIdx.x * 256 + tid;
    float s = 0.f;
    #pragma unroll
    for (int p = 0; p < KSPLIT; p++) s += g_part[p * (ALPHA * DIM) + o];
    g_Mth[o] = __float2half_rn(s * SCALE * MT_S);
    g_CVh[o] = __float2half_rn(C_V[o] * CV_S);
}

// ---------------- fused: 1 CTA = 128 rows, 256 threads, 2 CTAs/SM ----------------
__global__ __launch_bounds__(256, 2) void fused_mma(
    const float* __restrict__ x, const int* __restrict__ mask,
    float* __restrict__ out)
{
    extern __shared__ __align__(16) char sm[];
    __half* xs  = (__half*)(sm + XS_OFF);            // 2 bufs of 128*72
    __half* mts = (__half*)(sm + MTS_OFF);           // 2 bufs of 64*72
    float*  pm  = (float*)(sm + PM_OFF);             // [128][2] row max
    float*  ps  = (float*)(sm + PS_OFF);             // [128][2] row sum
    __half* ahs = (__half*)(sm + AH_OFF);
    __half* cvs = (__half*)(sm + CVS_OFF);           // 2 bufs of 64*72 (dedicated)
    float*  bsm = (float*)(sm + BIAS_OFF);

    const int tid  = threadIdx.x;
    const int lane = tid & 31, wid = tid >> 5;
    const int gid  = lane >> 2, tig = lane & 3;
    const int rg   = wid >> 1, ng = wid & 1;
    const int row0 = blockIdx.x * TILE_ROWS;

    if (tid < ALPHA) bsm[tid] = g_bias[tid];

    // ldmatrix per-lane coords
    const int arow = rg * 32 + (lane & 15);
    const int acol = (lane >> 4) * 8;
    const int brow = ng * 32 + (lane & 7) + ((lane >> 4) & 1) * 8;
    const int bcol = ((lane >> 3) & 1) * 8;

    // x loader coords: warp-contiguous (minimal L1 wavefronts)
    const int xrow = wid * 16 + (lane >> 4);         // + i*2
    const int xcol = (lane & 15) * 4;
    // cp.async tile coords: each thread copies 2 consecutive 16B units
    const int trow = (tid * 2) >> 3, tseg = (tid * 2) & 7;

    float4 xv[8];

    auto ldg_x = [&](int c) {
        const float* xp = x + (size_t)(row0 + xrow) * DIM + c * 64 + xcol;
        #pragma unroll
        for (int i = 0; i < 8; i++)
            xv[i] = *(const float4*)(xp + (size_t)(i * 2) * DIM);
    };
    auto sts_x = [&](int b) {
        __half* xd = xs + b * (128 * 72) + xrow * 72 + xcol;
        #pragma unroll
        for (int i = 0; i < 8; i++) {
            uint2 h;
            h.x = fpack(xv[i].x, xv[i].y);
            h.y = fpack(xv[i].z, xv[i].w);
            *(uint2*)(xd + i * 2 * 72) = h;
        }
    };
    auto cp_mt = [&](int c, int b) {
        char* dst = (char*)mts + b * 9216 + trow * 144 + tseg * 16;
        const char* src = (const char*)g_Mth + trow * 2048 + c * 128 + tseg * 16;
        cp_async16(dst, src);
        cp_async16(dst + 16, src + 16);
    };
    auto cp_cv = [&](int c, int b) {
        char* dst = (char*)cvs + b * 9216 + trow * 144 + tseg * 16;
        const char* src = (const char*)g_CVh + (size_t)(c * 64 + trow) * 128 + tseg * 16;
        cp_async16(dst, src);
        cp_async16(dst + 16, src + 16);
    };

    // ---- phase 1: logits = x @ Mt^T, 16 chunks of k=64 ----
    float acc1[2][4][4] = {};
    ldg_x(0);
    cp_mt(0, 0); CP_COMMIT();
    cp_mt(1, 1); CP_COMMIT();
    sts_x(0);
    ldg_x(1);
    CP_WAIT0();
    __syncthreads();
    for (int c = 0; c < 16; c++) {
        const __half* xb  = xs + (c & 1) * (128 * 72);
        const __half* mbf = mts + (c & 1) * (64 * 72);
        #pragma unroll
        for (int ks = 0; ks < 4; ks++) {
            uint32_t A0[2][4], B0[2][4];
            #pragma unroll
            for (int m = 0; m < 2; m++)
                ldsm_x4(A0[m], xb + (arow + m * 16) * 72 + ks * 16 + acol);
            #pragma unroll
            for (int nt = 0; nt < 2; nt++)
                ldsm_x4(B0[nt], mbf + (brow + nt * 16) * 72 + ks * 16 + bcol);
            #pragma unroll
            for (int nt = 0; nt < 2; nt++)
                #pragma unroll
                for (int m = 0; m < 2; m++) {
                    mma16816(acc1[m][nt * 2],     A0[m], &B0[nt][0]);
                    mma16816(acc1[m][nt * 2 + 1], A0[m], &B0[nt][2]);
                }
        }
        if (c < 15) sts_x((c + 1) & 1);
        CP_WAIT0();
        __syncthreads();
        if (c < 14) {
            cp_mt(c + 2, c & 1); CP_COMMIT();
            ldg_x(c + 2);
        }
    }
    // xs/mts dead from here (last sync covers mma(15) ldsm)

    // prefetch C_V chunks 0,1 (lands during softmax)
    cp_cv(0, 0); CP_COMMIT();
    cp_cv(1, 1); CP_COMMIT();

    // ---- phase 2: distributed softmax (quad shuffles + tiny smem exchange) ----
    // thread holds rows r(m,h) = rg*32 + m*16 + h*8 + gid, cols ng*32 + n*8 + tig*2 + b
    float bv[4][2];
    #pragma unroll
    for (int n = 0; n < 4; n++) {
        bv[n][0] = bsm[ng * 32 + n * 8 + tig * 2];
        bv[n][1] = bsm[ng * 32 + n * 8 + tig * 2 + 1];
    }
    float v[2][2][8];
    #pragma unroll
    for (int m = 0; m < 2; m++)
        #pragma unroll
        for (int h = 0; h < 2; h++) {
            float mx = -1e30f;
            #pragma unroll
            for (int n = 0; n < 4; n++)
                #pragma unroll
                for (int b = 0; b < 2; b++) {
                    const float t = acc1[m][n][h * 2 + b] * INV_MT + bv[n][b];
                    v[m][h][n * 2 + b] = t;
                    mx = fmaxf(mx, t);
                }
            mx = fmaxf(mx, __shfl_xor_sync(0xffffffffu, mx, 1));
            mx = fmaxf(mx, __shfl_xor_sync(0xffffffffu, mx, 2));
            if (tig == 0) pm[(rg * 32 + m * 16 + h * 8 + gid) * 2 + ng] = mx;
        }
    __syncthreads();
    float vsum[2][2];
    #pragma unroll
    for (int m = 0; m < 2; m++)
        #pragma unroll
        for (int h = 0; h < 2; h++) {
            const int r = rg * 32 + m * 16 + h * 8 + gid;
            const float mx = fmaxf(pm[r * 2], pm[r * 2 + 1]);
            float s = 0.f;
            #pragma unroll
            for (int j = 0; j < 8; j++) {
                const float e = __expf(v[m][h][j] - mx);
                v[m][h][j] = e;
                s += e;
            }
            s += __shfl_xor_sync(0xffffffffu, s, 1);
            s += __shfl_xor_sync(0xffffffffu, s, 2);
            vsum[m][h] = s;
            if (tig == 0) ps[r * 2 + ng] = s;
        }
    __syncthreads();
    #pragma unroll
    for (int m = 0; m < 2; m++)
        #pragma unroll
        for (int h = 0; h < 2; h++) {
            const int r = rg * 32 + m * 16 + h * 8 + gid;
            const float tot = ps[r * 2] + ps[r * 2 + 1];
            const float inv = (mask[row0 + r] ? A_S : 0.0f) / tot;
            __half* ahp = ahs + r * 72 + ng * 32 + tig * 2;
            #pragma unroll
            for (int n = 0; n < 4; n++)
                *(uint32_t*)(ahp + n * 8) =
                    fpack(v[m][h][n * 2] * inv, v[m][h][n * 2 + 1] * inv);
        }
    CP_WAIT0();
    __syncthreads();        // ahs ready; cv(0),cv(1) visible

    // ---- phase 3: out = A @ C_V^T, 16 chunks of 64 d ----
    uint32_t Ah[2][4][4];
    #pragma unroll
    for (int m = 0; m < 2; m++)
        #pragma unroll
        for (int ks = 0; ks < 4; ks++)
            ldsm_x4(Ah[m][ks], ahs + (arow + m * 16) * 72 + ks * 16 + acol);

    for (int c = 0; c < 16; c++) {
        const __half* ch = cvs + (c & 1) * (64 * 72);
        float acc[2][4][4] = {};
        #pragma unroll
        for (int ks = 0; ks < 4; ks++) {
            uint32_t Bh[2][4];
            #pragma unroll
            for (int nt = 0; nt < 2; nt++)
                ldsm_x4(Bh[nt], ch + (brow + nt * 16) * 72 + ks * 16 + bcol);
            #pragma unroll
            for (int nt = 0; nt < 2; nt++)
                #pragma unroll
                for (int m = 0; m < 2; m++) {
                    mma16816(acc[m][nt * 2],     Ah[m][ks], &Bh[nt][0]);
                    mma16816(acc[m][nt * 2 + 1], Ah[m][ks], &Bh[nt][2]);
                }
        }
        #pragma unroll
        for (int m = 0; m < 2; m++)
            #pragma unroll
            for (int n = 0; n < 4; n++) {
                const size_t r = (size_t)(row0 + rg * 32 + m * 16 + gid);
                const int d = c * 64 + ng * 32 + n * 8 + tig * 2;
                float* po = out + r * DIM + d;
                po[0] = acc[m][n][0] * OUT_S;
                po[1] = acc[m][n][1] * OUT_S;
                po[8 * DIM] = acc[m][n][2] * OUT_S;
                po[8 * DIM + 1] = acc[m][n][3] * OUT_S;
            }
        CP_WAIT0();
        __syncthreads();
        if (c < 14) { cp_cv(c + 2, c & 1); CP_COMMIT(); }
    }
}

// ---------------------------------------------------------------------------
extern "C" void kernel_launch(void* const* d_in, const int* in_sizes, int n_in,
                              void* d_out, int out_size)
{
    const float* x    = (const float*)d_in[0];
    const int*   mask = (const int*)d_in[1];
    const float* W_Q  = (const float*)d_in[2];
    const float* b_Q  = (const float*)d_in[3];
    const float* C_K  = (const float*)d_in[4];
    const float* C_V  = (const float*)d_in[5];
    float*       out  = (float*)d_out;

    cudaFuncSetAttribute(fused_mma, cudaFuncAttributeMaxDynamicSharedMemorySize, SMEM_BYTES);
    prep_partial<<<KSPLIT * 16, 256>>>(W_Q, C_K);
    prep_reduce<<<257, 256>>>(b_Q, C_K, C_V);
    fused_mma<<<NCTA, 256, SMEM_BYTES>>>(x, mask, out);
}